// round 1
// baseline (speedup 1.0000x reference)
#include <cuda_runtime.h>
#include <math.h>

// ---------------- scratch (static device memory; no allocation) ----------------
#define NTOK 32768
#define CFEAT 64

__device__ float g_t [NTOK * CFEAT];   // tokens [n][c]
__device__ float g_hT[NTOK * CFEAT];   // transposed [c][n]
__device__ float g_qs[NTOK * CFEAT];
__device__ float g_ks[NTOK * CFEAT];
__device__ float g_vs[NTOK * CFEAT];
__device__ int   g_idx[NTOK];
__device__ int   g_M;

// ---------------- patch conv: x[128^3] -> t[n][c] (no pos yet) ----------------
__global__ void conv_kernel(const float* __restrict__ x,
                            const float* __restrict__ W,   // [64][64]
                            const float* __restrict__ b)
{
    int n0  = blockIdx.x * 8;
    int tid = threadIdx.x;          // 64 threads, one output channel each
    __shared__ float patch[8][64];

    int dz = tid >> 4, dy = (tid >> 2) & 3, dx = tid & 3;
    #pragma unroll
    for (int v = 0; v < 8; ++v) {
        int n = n0 + v;
        int z = n >> 10, y = (n >> 5) & 31, xx = n & 31;
        patch[v][tid] = x[(4*z + dz) * 16384 + (4*y + dy) * 128 + (4*xx + dx)];
    }
    __syncthreads();

    float w[64];
    const float4* wp = (const float4*)(W + tid * 64);
    #pragma unroll
    for (int i = 0; i < 16; ++i) {
        float4 t4 = wp[i];
        w[4*i] = t4.x; w[4*i+1] = t4.y; w[4*i+2] = t4.z; w[4*i+3] = t4.w;
    }
    float bv = b[tid];

    #pragma unroll
    for (int v = 0; v < 8; ++v) {
        float acc = bv;
        #pragma unroll
        for (int k = 0; k < 64; ++k) acc += patch[v][k] * w[k];
        g_t[(n0 + v) * 64 + tid] = acc;
    }
}

// ---------------- pos-embed add: t[n][c] += pos[c][n] (tiled transpose) --------
__global__ void pos_add_kernel(const float* __restrict__ pos)
{
    __shared__ float tile[32][33];
    int n0 = blockIdx.x * 32;
    int c0 = blockIdx.y * 32;
    int tx = threadIdx.x, ty = threadIdx.y;
    tile[ty][tx] = pos[(c0 + ty) * NTOK + n0 + tx];
    __syncthreads();
    g_t[(n0 + ty) * 64 + c0 + tx] += tile[tx][ty];
}

// ---------------- dilation index build (matches numpy f32 exactly) -------------
__global__ void build_idx_kernel(int dil)
{
    __shared__ int cnt[1024];
    int t = threadIdx.x;
    int base = t * 32;
    float fd = (float)dil;

    unsigned flags = 0; int c = 0;
    for (int j = 0; j < 32; ++j) {
        int n = base + j;
        int z = (n >> 10) - 16, y = ((n >> 5) & 31) - 16, x = (n & 31) - 16;
        int ss = z*z + y*y + x*x;
        float d = sqrtf((float)ss);
        bool ok = (fmodf(d, fd) == 0.0f) || (ss == 0);
        if (ok) { flags |= (1u << j); c++; }
    }
    cnt[t] = c;
    __syncthreads();
    for (int off = 1; off < 1024; off <<= 1) {
        int v = (t >= off) ? cnt[t - off] : 0;
        __syncthreads();
        cnt[t] += v;
        __syncthreads();
    }
    int pos = cnt[t] - c;
    for (int j = 0; j < 32; ++j)
        if (flags & (1u << j)) g_idx[pos++] = base + j;
    if (t == 1023) g_M = cnt[1023];
}

// ---------------- QKV for selected tokens (scale 1/8 folded into Q, exact) -----
__global__ void qkv_kernel(const float* __restrict__ W,    // [192][64]
                           const float* __restrict__ bias) // [192]
{
    int M   = g_M;
    int tid = threadIdx.x;   // 192 threads, one output channel each
    __shared__ float Ts[32][68];

    float w[64];
    const float4* wr = (const float4*)(W + tid * 64);
    #pragma unroll
    for (int i = 0; i < 16; ++i) {
        float4 t4 = wr[i];
        w[4*i] = t4.x; w[4*i+1] = t4.y; w[4*i+2] = t4.z; w[4*i+3] = t4.w;
    }
    float bv = bias[tid];

    for (int m0 = blockIdx.x * 32; m0 < M; m0 += gridDim.x * 32) {
        __syncthreads();
        for (int e = tid; e < 32 * 64; e += 192) {
            int ml = e >> 6, k = e & 63;
            int m = m0 + ml;
            Ts[ml][k] = (m < M) ? g_t[g_idx[m] * 64 + k] : 0.f;
        }
        __syncthreads();
        int mmax = min(32, M - m0);
        for (int ml = 0; ml < mmax; ++ml) {
            float acc = bv;
            #pragma unroll
            for (int k = 0; k < 64; ++k) acc += Ts[ml][k] * w[k];
            int m = m0 + ml;
            if      (tid <  64) g_qs[m * 64 + tid]       = acc * 0.125f;
            else if (tid < 128) g_ks[m * 64 + tid - 64]  = acc;
            else                g_vs[m * 64 + tid - 128] = acc;
        }
    }
}

// ---------------- fused attention + proj + residual + scatter ------------------
// TILE_M=32 queries/block, TILE_N=64 key tile, 256 threads.
// thread layout: row r = tid>>3 (0..31), lane-in-row qq = tid&7.
__global__ void attn_kernel(const float* __restrict__ Wp,  // [64][64]
                            const float* __restrict__ bp)  // [64]
{
    int M   = g_M;
    int tid = threadIdx.x;        // 256
    int r   = tid >> 3;
    int qq  = tid & 7;

    __shared__ float Ksm[64][68];
    __shared__ float Vsm[64][68];
    __shared__ float Psm[32][65];
    float* Ysm = &Ksm[0][0];      // reuse K region after mainloop (stride 65)

    for (int m0 = blockIdx.x * 32; m0 < M; m0 += gridDim.x * 32) {
        int  m     = m0 + r;
        bool valid = (m < M);

        float qreg[64];
        {
            const float4* qp = (const float4*)(g_qs + (valid ? m : 0) * 64);
            #pragma unroll
            for (int i = 0; i < 16; ++i) {
                float4 v = qp[i];
                qreg[4*i] = v.x; qreg[4*i+1] = v.y; qreg[4*i+2] = v.z; qreg[4*i+3] = v.w;
            }
        }
        float y[8];
        #pragma unroll
        for (int j = 0; j < 8; ++j) y[j] = 0.f;
        float row_max = -1e30f, row_sum = 0.f;

        for (int n0 = 0; n0 < M; n0 += 64) {
            __syncthreads();                       // smem reuse guard
            for (int e = tid; e < 64 * 64; e += 256) {
                int nl = e >> 6, k = e & 63;
                int n = n0 + nl;
                float kv = 0.f, vv = 0.f;
                if (n < M) { kv = g_ks[n * 64 + k]; vv = g_vs[n * 64 + k]; }
                Ksm[nl][k] = kv;
                Vsm[nl][k] = vv;
            }
            __syncthreads();

            float s[8];
            float tmax = -1e30f;
            #pragma unroll
            for (int kk = 0; kk < 8; ++kk) {
                int nl = qq + 8 * kk;
                float acc = 0.f;
                #pragma unroll
                for (int k = 0; k < 64; ++k) acc += qreg[k] * Ksm[nl][k];
                if (n0 + nl >= M) acc = -1e30f;
                s[kk] = acc;
                tmax = fmaxf(tmax, acc);
            }
            #pragma unroll
            for (int o = 1; o < 8; o <<= 1)
                tmax = fmaxf(tmax, __shfl_xor_sync(0xffffffffu, tmax, o));

            float nmax = fmaxf(row_max, tmax);
            float corr = expf(row_max - nmax);
            float lsum = 0.f;
            #pragma unroll
            for (int kk = 0; kk < 8; ++kk) {
                float p = expf(s[kk] - nmax);
                Psm[r][qq + 8 * kk] = p;
                lsum += p;
            }
            #pragma unroll
            for (int o = 1; o < 8; o <<= 1)
                lsum += __shfl_xor_sync(0xffffffffu, lsum, o);
            row_sum = row_sum * corr + lsum;
            row_max = nmax;
            #pragma unroll
            for (int j = 0; j < 8; ++j) y[j] *= corr;
            __syncwarp();

            for (int nl = 0; nl < 64; ++nl) {
                float p = Psm[r][nl];
                #pragma unroll
                for (int j = 0; j < 8; ++j) y[j] += p * Vsm[nl][qq + 8 * j];
            }
        }

        float inv = 1.0f / row_sum;
        __syncthreads();               // everyone done reading Ksm
        if (valid) {
            #pragma unroll
            for (int j = 0; j < 8; ++j) Ysm[r * 65 + qq + 8 * j] = y[j] * inv;
        }
        __syncthreads();

        // proj + residual + scatter: out[r][oc] = Y@Wp^T + bp + Y
        int oc = tid & 63;
        int rb = tid >> 6;             // 0..3
        float wrow[64];
        {
            const float4* wr = (const float4*)(Wp + oc * 64);
            #pragma unroll
            for (int i = 0; i < 16; ++i) {
                float4 v = wr[i];
                wrow[4*i] = v.x; wrow[4*i+1] = v.y; wrow[4*i+2] = v.z; wrow[4*i+3] = v.w;
            }
        }
        float bv = bp[oc];
        int mmax = min(32, M - m0);
        for (int rr = rb; rr < mmax; rr += 4) {
            float acc = bv;
            #pragma unroll
            for (int k = 0; k < 64; ++k) acc += Ysm[rr * 65 + k] * wrow[k];
            acc += Ysm[rr * 65 + oc];
            g_t[g_idx[m0 + rr] * 64 + oc] = acc;
        }
    }
}

// ---------------- transpose t[n][c] -> hT[c][n] --------------------------------
__global__ void transpose_kernel()
{
    __shared__ float tile[32][33];
    int n0 = blockIdx.x * 32;
    int c0 = blockIdx.y * 32;
    int tx = threadIdx.x, ty = threadIdx.y;
    tile[ty][tx] = g_t[(n0 + ty) * 64 + c0 + tx];
    __syncthreads();
    g_hT[(c0 + ty) * NTOK + n0 + tx] = tile[tx][ty];
}

// ---------------- trilinear x4 upsample: hT[c][32^3] -> out[c][128^3] ----------
__global__ void upsample_kernel(float* __restrict__ out)
{
    const float S = 31.0f / 127.0f;
    int zo  = blockIdx.x;    // 0..127
    int c   = blockIdx.y;    // 0..63
    int tid = threadIdx.x;   // 256

    float pz = (float)zo * S;
    int z0 = (int)pz;
    int z1 = min(z0 + 1, 31);
    float wz = pz - (float)z0;

    __shared__ float F[1024];      // z-fused source plane [y][x]
    __shared__ float R[8][33];     // per-warp y-lerped row

    const float* p0 = g_hT + c * NTOK + z0 * 1024;
    const float* p1 = g_hT + c * NTOK + z1 * 1024;
    for (int i = tid; i < 1024; i += 256) {
        float a = p0[i];
        F[i] = a + wz * (p1[i] - a);
    }
    __syncthreads();

    int w = tid >> 5, lane = tid & 31;
    size_t obase = ((size_t)(c * 128 + zo)) * 16384;

    for (int it = 0; it < 16; ++it) {
        int yo = it * 8 + w;
        float py = (float)yo * S;
        int y0 = (int)py;
        int y1 = min(y0 + 1, 31);
        float wy = py - (float)y0;

        float a = F[y0 * 32 + lane];
        float b = F[y1 * 32 + lane];
        R[w][lane] = a + wy * (b - a);
        __syncwarp();

        float4 o;
        #pragma unroll
        for (int j = 0; j < 4; ++j) {
            int xo = lane * 4 + j;
            float px = (float)xo * S;
            int x0 = (int)px;
            int x1 = min(x0 + 1, 31);
            float wx = px - (float)x0;
            float r0 = R[w][x0];
            (&o.x)[j] = r0 + wx * (R[w][x1] - r0);
        }
        *(float4*)(out + obase + (size_t)yo * 128 + lane * 4) = o;
        __syncwarp();
    }
}

// ---------------- launch --------------------------------------------------------
extern "C" void kernel_launch(void* const* d_in, const int* in_sizes, int n_in,
                              void* d_out, int out_size)
{
    const float* x       = (const float*)d_in[0];
    const float* w_patch = (const float*)d_in[1];
    const float* b_patch = (const float*)d_in[2];
    const float* pos     = (const float*)d_in[3];

    const float* qkv_w[3]  = { (const float*)d_in[4],  (const float*)d_in[8],  (const float*)d_in[12] };
    const float* qkv_b[3]  = { (const float*)d_in[5],  (const float*)d_in[9],  (const float*)d_in[13] };
    const float* proj_w[3] = { (const float*)d_in[6],  (const float*)d_in[10], (const float*)d_in[14] };
    const float* proj_b[3] = { (const float*)d_in[7],  (const float*)d_in[11], (const float*)d_in[15] };

    conv_kernel<<<NTOK / 8, 64>>>(x, w_patch, b_patch);
    pos_add_kernel<<<dim3(NTOK / 32, 2), dim3(32, 32)>>>(pos);

    const int dils[3] = {2, 4, 6};
    for (int i = 0; i < 3; ++i) {
        build_idx_kernel<<<1, 1024>>>(dils[i]);
        qkv_kernel<<<128, 192>>>(qkv_w[i], qkv_b[i]);
        attn_kernel<<<128, 256>>>(proj_w[i], proj_b[i]);
    }

    transpose_kernel<<<dim3(NTOK / 32, 2), dim3(32, 32)>>>();
    upsample_kernel<<<dim3(128, 64), 256>>>((float*)d_out);
}

// round 2
// speedup vs baseline: 1.0889x; 1.0889x over previous
#include <cuda_runtime.h>
#include <math.h>

#define NTOK 32768
#define CFEAT 64

// ---------------- scratch (static device memory; no allocation) ----------------
__device__ float g_t  [NTOK * CFEAT];   // tokens [n][c]
__device__ float g_hT [NTOK * CFEAT];   // channel-major [c][n]
__device__ float g_qs [NTOK * CFEAT];
__device__ float g_ks [NTOK * CFEAT];
__device__ float g_vs [NTOK * CFEAT];
__device__ int   g_idx3[3 * NTOK];
__device__ int   g_M3[3];

// ---------------- fused patch conv + pos embed, dual-layout write --------------
// block = 32 tokens, 256 threads. Output written to g_t [n][c] AND g_hT [c][n].
__global__ void __launch_bounds__(256) conv_pos_kernel(
    const float* __restrict__ x,
    const float* __restrict__ W,    // [64][64]
    const float* __restrict__ b,
    const float* __restrict__ pos)  // [64][32768]
{
    __shared__ float P[32][68];     // patches [tok][k], 16B-aligned rows
    __shared__ float O[64][33];     // results [c][tok]
    int n0  = blockIdx.x * 32;
    int tid = threadIdx.x;

    #pragma unroll
    for (int j = 0; j < 8; ++j) {
        int e   = tid + 256 * j;
        int tok = e >> 6, k = e & 63;
        int n = n0 + tok;
        int z = n >> 10, y = (n >> 5) & 31, xx = n & 31;
        int dz = k >> 4, dy = (k >> 2) & 3, dx = k & 3;
        P[tok][k] = x[(4*z + dz) * 16384 + (4*y + dy) * 128 + (4*xx + dx)];
    }
    __syncthreads();

    int c = tid >> 2, sub = tid & 3;      // thread: channel c, tokens sub+4u
    float w[64];
    {
        const float4* wp = (const float4*)(W + c * 64);
        #pragma unroll
        for (int i = 0; i < 16; ++i) {
            float4 t4 = wp[i];
            w[4*i] = t4.x; w[4*i+1] = t4.y; w[4*i+2] = t4.z; w[4*i+3] = t4.w;
        }
    }
    float bv = b[c];
    float acc[8];
    #pragma unroll
    for (int u = 0; u < 8; ++u) acc[u] = bv;

    #pragma unroll
    for (int k4 = 0; k4 < 16; ++k4) {
        #pragma unroll
        for (int u = 0; u < 8; ++u) {
            float4 p = *(const float4*)&P[u * 4 + sub][k4 * 4];
            acc[u] += p.x * w[4*k4];
            acc[u] += p.y * w[4*k4+1];
            acc[u] += p.z * w[4*k4+2];
            acc[u] += p.w * w[4*k4+3];
        }
    }
    #pragma unroll
    for (int u = 0; u < 8; ++u) O[c][u * 4 + sub] = acc[u];
    __syncthreads();

    // add pos (in-place in O) and write g_hT coalesced: idx = c*32 + nl
    #pragma unroll
    for (int j = 0; j < 8; ++j) {
        int e  = tid + 256 * j;
        int cc = e >> 5, nl = e & 31;
        float v = O[cc][nl] + pos[cc * NTOK + n0 + nl];
        O[cc][nl] = v;
        g_hT[cc * NTOK + n0 + nl] = v;
    }
    __syncthreads();

    // write g_t [n][c] coalesced: idx = nl*64 + c
    #pragma unroll
    for (int j = 0; j < 8; ++j) {
        int e  = tid + 256 * j;
        int nl = e >> 6, cc = e & 63;
        g_t[(n0 + nl) * 64 + cc] = O[cc][nl];
    }
}

// ---------------- dilation index build: 3 blocks, one per dilation -------------
__global__ void build_idx3_kernel()
{
    __shared__ int cnt[1024];
    int bi  = blockIdx.x;
    int dil = (bi == 0) ? 2 : (bi == 1) ? 4 : 6;
    int*  out = g_idx3 + bi * NTOK;
    int t = threadIdx.x;
    int base = t * 32;
    float fd = (float)dil;

    unsigned flags = 0; int c = 0;
    for (int j = 0; j < 32; ++j) {
        int n = base + j;
        int z = (n >> 10) - 16, y = ((n >> 5) & 31) - 16, x = (n & 31) - 16;
        int ss = z*z + y*y + x*x;
        float d = sqrtf((float)ss);
        bool ok = (fmodf(d, fd) == 0.0f) || (ss == 0);
        if (ok) { flags |= (1u << j); c++; }
    }
    cnt[t] = c;
    __syncthreads();
    for (int off = 1; off < 1024; off <<= 1) {
        int v = (t >= off) ? cnt[t - off] : 0;
        __syncthreads();
        cnt[t] += v;
        __syncthreads();
    }
    int pos = cnt[t] - c;
    for (int j = 0; j < 32; ++j)
        if (flags & (1u << j)) out[pos++] = base + j;
    if (t == 1023) g_M3[bi] = cnt[1023];
}

// ---------------- QKV for selected tokens (scale 1/8 folded into Q) ------------
__global__ void __launch_bounds__(192) qkv_kernel(
    const float* __restrict__ W,    // [192][64]
    const float* __restrict__ bias, // [192]
    int bi)
{
    int M = g_M3[bi];
    if ((int)blockIdx.x * 32 >= M) return;
    const int* __restrict__ idx = g_idx3 + bi * NTOK;

    int tid = threadIdx.x;   // 192: one output channel each
    __shared__ float Ts[32][68];

    float w[64];
    {
        const float4* wr = (const float4*)(W + tid * 64);
        #pragma unroll
        for (int i = 0; i < 16; ++i) {
            float4 t4 = wr[i];
            w[4*i] = t4.x; w[4*i+1] = t4.y; w[4*i+2] = t4.z; w[4*i+3] = t4.w;
        }
    }
    float bv = bias[tid];

    for (int m0 = blockIdx.x * 32; m0 < M; m0 += gridDim.x * 32) {
        __syncthreads();
        for (int e = tid; e < 32 * 64; e += 192) {
            int ml = e >> 6, k = e & 63;
            int m = m0 + ml;
            Ts[ml][k] = (m < M) ? g_t[idx[m] * 64 + k] : 0.f;
        }
        __syncthreads();
        int mmax = min(32, M - m0);

        #pragma unroll
        for (int ml0 = 0; ml0 < 32; ml0 += 8) {
            float acc[8];
            #pragma unroll
            for (int u = 0; u < 8; ++u) acc[u] = bv;
            #pragma unroll
            for (int k4 = 0; k4 < 16; ++k4) {
                #pragma unroll
                for (int u = 0; u < 8; ++u) {
                    float4 t4 = *(const float4*)&Ts[ml0 + u][k4 * 4];
                    acc[u] += t4.x * w[4*k4];
                    acc[u] += t4.y * w[4*k4+1];
                    acc[u] += t4.z * w[4*k4+2];
                    acc[u] += t4.w * w[4*k4+3];
                }
            }
            #pragma unroll
            for (int u = 0; u < 8; ++u) {
                int ml = ml0 + u;
                if (ml < mmax) {
                    int m = m0 + ml;
                    if      (tid <  64) g_qs[m * 64 + tid]       = acc[u] * 0.125f;
                    else if (tid < 128) g_ks[m * 64 + tid - 64]  = acc[u];
                    else                g_vs[m * 64 + tid - 128] = acc[u];
                }
            }
        }
    }
}

// ---------------- fused attention + proj + residual + dual scatter -------------
// 32 queries/block, 64-key tiles, 256 threads. thread: row r = tid>>3,
// channel group cb = (tid&7)*8 (8 contiguous channels).
__global__ void __launch_bounds__(256) attn_kernel(
    const float* __restrict__ Wp,  // [64][64]
    const float* __restrict__ bp,  // [64]
    int bi)
{
    int M = g_M3[bi];
    if ((int)blockIdx.x * 32 >= M) return;
    const int* __restrict__ idx = g_idx3 + bi * NTOK;

    int tid = threadIdx.x;
    int r   = tid >> 3;
    int qq  = tid & 7;
    int cb  = qq * 8;

    __shared__ float Ksm[64][68];
    __shared__ float Vsm[64][68];
    __shared__ float Psm[32][65];
    float* Ysm = &Ksm[0][0];          // reuse K region after mainloop, stride 68

    for (int m0 = blockIdx.x * 32; m0 < M; m0 += gridDim.x * 32) {
        int  m     = m0 + r;
        bool valid = (m < M);

        float qreg[64];
        {
            const float4* qp = (const float4*)(g_qs + (valid ? m : 0) * 64);
            #pragma unroll
            for (int i = 0; i < 16; ++i) {
                float4 v = qp[i];
                qreg[4*i] = v.x; qreg[4*i+1] = v.y; qreg[4*i+2] = v.z; qreg[4*i+3] = v.w;
            }
        }
        float y[8];
        #pragma unroll
        for (int j = 0; j < 8; ++j) y[j] = 0.f;
        float row_max = -1e30f, row_sum = 0.f;

        for (int n0 = 0; n0 < M; n0 += 64) {
            __syncthreads();
            for (int e = tid; e < 64 * 16; e += 256) {   // float4 granularity
                int nl = e >> 4, k4 = e & 15;
                int n = n0 + nl;
                float4 kv = make_float4(0.f, 0.f, 0.f, 0.f);
                float4 vv = kv;
                if (n < M) {
                    kv = *(const float4*)(g_ks + n * 64 + k4 * 4);
                    vv = *(const float4*)(g_vs + n * 64 + k4 * 4);
                }
                *(float4*)&Ksm[nl][k4 * 4] = kv;
                *(float4*)&Vsm[nl][k4 * 4] = vv;
            }
            __syncthreads();

            float s[8];
            float tmax = -1e30f;
            #pragma unroll
            for (int kk = 0; kk < 8; ++kk) {
                int nl = 8 * kk + qq;                 // consecutive rows per warp
                float acc = 0.f;
                #pragma unroll
                for (int k4 = 0; k4 < 16; ++k4) {
                    float4 kvec = *(const float4*)&Ksm[nl][k4 * 4];
                    acc += qreg[4*k4]   * kvec.x;
                    acc += qreg[4*k4+1] * kvec.y;
                    acc += qreg[4*k4+2] * kvec.z;
                    acc += qreg[4*k4+3] * kvec.w;
                }
                if (n0 + nl >= M) acc = -1e30f;
                s[kk] = acc;
                tmax = fmaxf(tmax, acc);
            }
            #pragma unroll
            for (int o = 1; o < 8; o <<= 1)
                tmax = fmaxf(tmax, __shfl_xor_sync(0xffffffffu, tmax, o));

            float nmax = fmaxf(row_max, tmax);
            float corr = expf(row_max - nmax);
            float lsum = 0.f;
            #pragma unroll
            for (int kk = 0; kk < 8; ++kk) {
                float p = expf(s[kk] - nmax);
                Psm[r][8 * kk + qq] = p;
                lsum += p;
            }
            #pragma unroll
            for (int o = 1; o < 8; o <<= 1)
                lsum += __shfl_xor_sync(0xffffffffu, lsum, o);
            row_sum = row_sum * corr + lsum;
            row_max = nmax;
            #pragma unroll
            for (int j = 0; j < 8; ++j) y[j] *= corr;
            __syncwarp();

            for (int nl = 0; nl < 64; ++nl) {
                float p = Psm[r][nl];
                float4 v0 = *(const float4*)&Vsm[nl][cb];
                float4 v1 = *(const float4*)&Vsm[nl][cb + 4];
                y[0] += p * v0.x; y[1] += p * v0.y;
                y[2] += p * v0.z; y[3] += p * v0.w;
                y[4] += p * v1.x; y[5] += p * v1.y;
                y[6] += p * v1.z; y[7] += p * v1.w;
            }
        }

        float inv = 1.0f / row_sum;
        __syncthreads();               // everyone done reading Ksm
        if (valid) {
            float4 o0 = make_float4(y[0]*inv, y[1]*inv, y[2]*inv, y[3]*inv);
            float4 o1 = make_float4(y[4]*inv, y[5]*inv, y[6]*inv, y[7]*inv);
            *(float4*)&Ysm[r * 68 + cb]     = o0;
            *(float4*)&Ysm[r * 68 + cb + 4] = o1;
        }
        __syncthreads();

        // proj + residual + dual scatter
        int oc = tid & 63;
        int rb = tid >> 6;             // 0..3
        float wrow[64];
        {
            const float4* wr = (const float4*)(Wp + oc * 64);
            #pragma unroll
            for (int i = 0; i < 16; ++i) {
                float4 v = wr[i];
                wrow[4*i] = v.x; wrow[4*i+1] = v.y; wrow[4*i+2] = v.z; wrow[4*i+3] = v.w;
            }
        }
        float bv = bp[oc];
        int mmax = min(32, M - m0);
        for (int rr = rb; rr < mmax; rr += 8) {
            int  rr2 = rr + 4;
            bool h2  = rr2 < mmax;
            int  rrs = h2 ? rr2 : rr;
            float a0 = bv, a1 = bv;
            #pragma unroll
            for (int k4 = 0; k4 < 16; ++k4) {
                float4 y0 = *(const float4*)&Ysm[rr  * 68 + k4 * 4];
                float4 y1 = *(const float4*)&Ysm[rrs * 68 + k4 * 4];
                a0 += y0.x * wrow[4*k4];   a1 += y1.x * wrow[4*k4];
                a0 += y0.y * wrow[4*k4+1]; a1 += y1.y * wrow[4*k4+1];
                a0 += y0.z * wrow[4*k4+2]; a1 += y1.z * wrow[4*k4+2];
                a0 += y0.w * wrow[4*k4+3]; a1 += y1.w * wrow[4*k4+3];
            }
            a0 += Ysm[rr  * 68 + oc];
            a1 += Ysm[rrs * 68 + oc];
            int tok0 = idx[m0 + rr];
            g_t [tok0 * 64 + oc]  = a0;
            g_hT[oc * NTOK + tok0] = a0;
            if (h2) {
                int tok1 = idx[m0 + rr2];
                g_t [tok1 * 64 + oc]  = a1;
                g_hT[oc * NTOK + tok1] = a1;
            }
        }
    }
}

// ---------------- trilinear x4 upsample: hT[c][32^3] -> out[c][128^3] ----------
__global__ void __launch_bounds__(256) upsample_kernel(float* __restrict__ out)
{
    const float S = 31.0f / 127.0f;
    int zo  = blockIdx.x;    // 0..127
    int c   = blockIdx.y;    // 0..63
    int tid = threadIdx.x;   // 256

    float pz = (float)zo * S;
    int z0 = (int)pz;
    int z1 = min(z0 + 1, 31);
    float wz = pz - (float)z0;

    __shared__ float F[1024];       // z-fused source plane [y][x]
    __shared__ float R[128][33];    // all y-lerped rows

    const float* p0 = g_hT + c * NTOK + z0 * 1024;
    const float* p1 = g_hT + c * NTOK + z1 * 1024;
    #pragma unroll
    for (int j = 0; j < 4; ++j) {
        int i = tid + 256 * j;
        float a = p0[i];
        F[i] = a + wz * (p1[i] - a);
    }
    __syncthreads();

    int w = tid >> 5, lane = tid & 31;

    // all 128 y-lerped rows up front (one sync total)
    #pragma unroll
    for (int j = 0; j < 16; ++j) {
        int yo = j * 8 + w;
        float py = (float)yo * S;
        int y0 = (int)py;
        int y1 = min(y0 + 1, 31);
        float wy = py - (float)y0;
        float a = F[y0 * 32 + lane];
        float b = F[y1 * 32 + lane];
        R[yo][lane] = a + wy * (b - a);
    }
    __syncthreads();

    // hoisted x weights
    int   x0[4], x1[4];
    float wx[4];
    #pragma unroll
    for (int j = 0; j < 4; ++j) {
        int xo = lane * 4 + j;
        float px = (float)xo * S;
        x0[j] = (int)px;
        x1[j] = min(x0[j] + 1, 31);
        wx[j] = px - (float)x0[j];
    }

    size_t obase = ((size_t)(c * 128 + zo)) * 16384;
    #pragma unroll
    for (int it = 0; it < 16; ++it) {
        int yo = it * 8 + w;
        const float* Rr = &R[yo][0];
        float4 o;
        #pragma unroll
        for (int j = 0; j < 4; ++j) {
            float r0 = Rr[x0[j]];
            (&o.x)[j] = r0 + wx[j] * (Rr[x1[j]] - r0);
        }
        *(float4*)(out + obase + (size_t)yo * 128 + lane * 4) = o;
    }
}

// ---------------- launch --------------------------------------------------------
extern "C" void kernel_launch(void* const* d_in, const int* in_sizes, int n_in,
                              void* d_out, int out_size)
{
    const float* x       = (const float*)d_in[0];
    const float* w_patch = (const float*)d_in[1];
    const float* b_patch = (const float*)d_in[2];
    const float* pos     = (const float*)d_in[3];

    const float* qkv_w[3]  = { (const float*)d_in[4],  (const float*)d_in[8],  (const float*)d_in[12] };
    const float* qkv_b[3]  = { (const float*)d_in[5],  (const float*)d_in[9],  (const float*)d_in[13] };
    const float* proj_w[3] = { (const float*)d_in[6],  (const float*)d_in[10], (const float*)d_in[14] };
    const float* proj_b[3] = { (const float*)d_in[7],  (const float*)d_in[11], (const float*)d_in[15] };

    conv_pos_kernel<<<NTOK / 32, 256>>>(x, w_patch, b_patch, pos);
    build_idx3_kernel<<<3, 1024>>>();

    for (int i = 0; i < 3; ++i) {
        qkv_kernel<<<16, 192>>>(qkv_w[i], qkv_b[i], i);
        attn_kernel<<<16, 256>>>(proj_w[i], proj_b[i], i);
    }

    upsample_kernel<<<dim3(128, 64), 256>>>((float*)d_out);
}

// round 3
// speedup vs baseline: 1.2521x; 1.1499x over previous
#include <cuda_runtime.h>
#include <math.h>

#define NTOK 32768
#define CFEAT 64
#define NSPLIT 8

// ---------------- scratch (static device memory; no allocation) ----------------
__device__ float g_t  [NTOK * CFEAT];   // tokens [n][c]
__device__ float g_hT [NTOK * CFEAT];   // channel-major [c][n]
__device__ float g_qs [NTOK * CFEAT];
__device__ float g_ks [NTOK * CFEAT];
__device__ float g_vs [NTOK * CFEAT];
__device__ int   g_idx3[3 * NTOK];
__device__ int   g_M3[3];
// split-K partials: [m_tile up to 1024][split 8][row 32][68: 64 y, m, l]
__device__ float g_part[(NTOK / 32) * NSPLIT * 32 * 68];

// ---------------- fused patch conv + pos embed, dual-layout write --------------
__global__ void __launch_bounds__(256) conv_pos_kernel(
    const float* __restrict__ x,
    const float* __restrict__ W,    // [64][64]
    const float* __restrict__ b,
    const float* __restrict__ pos)  // [64][32768]
{
    __shared__ float P[32][68];
    __shared__ float O[64][33];
    int n0  = blockIdx.x * 32;
    int tid = threadIdx.x;

    #pragma unroll
    for (int j = 0; j < 8; ++j) {
        int e   = tid + 256 * j;
        int tok = e >> 6, k = e & 63;
        int n = n0 + tok;
        int z = n >> 10, y = (n >> 5) & 31, xx = n & 31;
        int dz = k >> 4, dy = (k >> 2) & 3, dx = k & 3;
        P[tok][k] = x[(4*z + dz) * 16384 + (4*y + dy) * 128 + (4*xx + dx)];
    }
    __syncthreads();

    int c = tid >> 2, sub = tid & 3;
    float w[64];
    {
        const float4* wp = (const float4*)(W + c * 64);
        #pragma unroll
        for (int i = 0; i < 16; ++i) {
            float4 t4 = wp[i];
            w[4*i] = t4.x; w[4*i+1] = t4.y; w[4*i+2] = t4.z; w[4*i+3] = t4.w;
        }
    }
    float bv = b[c];
    float acc[8];
    #pragma unroll
    for (int u = 0; u < 8; ++u) acc[u] = bv;

    #pragma unroll
    for (int k4 = 0; k4 < 16; ++k4) {
        #pragma unroll
        for (int u = 0; u < 8; ++u) {
            float4 p = *(const float4*)&P[u * 4 + sub][k4 * 4];
            acc[u] += p.x * w[4*k4];
            acc[u] += p.y * w[4*k4+1];
            acc[u] += p.z * w[4*k4+2];
            acc[u] += p.w * w[4*k4+3];
        }
    }
    #pragma unroll
    for (int u = 0; u < 8; ++u) O[c][u * 4 + sub] = acc[u];
    __syncthreads();

    #pragma unroll
    for (int j = 0; j < 8; ++j) {
        int e  = tid + 256 * j;
        int cc = e >> 5, nl = e & 31;
        float v = O[cc][nl] + pos[cc * NTOK + n0 + nl];
        O[cc][nl] = v;
        g_hT[cc * NTOK + n0 + nl] = v;
    }
    __syncthreads();

    #pragma unroll
    for (int j = 0; j < 8; ++j) {
        int e  = tid + 256 * j;
        int nl = e >> 6, cc = e & 63;
        g_t[(n0 + nl) * 64 + cc] = O[cc][nl];
    }
}

// ---------------- dilation index build: 3 blocks, one per dilation -------------
__global__ void build_idx3_kernel()
{
    __shared__ int cnt[1024];
    int bi  = blockIdx.x;
    int dil = (bi == 0) ? 2 : (bi == 1) ? 4 : 6;
    int*  out = g_idx3 + bi * NTOK;
    int t = threadIdx.x;
    int base = t * 32;
    float fd = (float)dil;

    unsigned flags = 0; int c = 0;
    for (int j = 0; j < 32; ++j) {
        int n = base + j;
        int z = (n >> 10) - 16, y = ((n >> 5) & 31) - 16, x = (n & 31) - 16;
        int ss = z*z + y*y + x*x;
        float d = sqrtf((float)ss);
        bool ok = (fmodf(d, fd) == 0.0f) || (ss == 0);
        if (ok) { flags |= (1u << j); c++; }
    }
    cnt[t] = c;
    __syncthreads();
    for (int off = 1; off < 1024; off <<= 1) {
        int v = (t >= off) ? cnt[t - off] : 0;
        __syncthreads();
        cnt[t] += v;
        __syncthreads();
    }
    int pos = cnt[t] - c;
    for (int j = 0; j < 32; ++j)
        if (flags & (1u << j)) out[pos++] = base + j;
    if (t == 1023) g_M3[bi] = cnt[1023];
}

// ---------------- QKV for selected tokens (scale 1/8 folded into Q) ------------
__global__ void __launch_bounds__(192) qkv_kernel(
    const float* __restrict__ W,    // [192][64]
    const float* __restrict__ bias, // [192]
    int bi)
{
    int M = g_M3[bi];
    if ((int)blockIdx.x * 32 >= M) return;
    const int* __restrict__ idx = g_idx3 + bi * NTOK;

    int tid = threadIdx.x;
    __shared__ float Ts[32][68];

    float w[64];
    {
        const float4* wr = (const float4*)(W + tid * 64);
        #pragma unroll
        for (int i = 0; i < 16; ++i) {
            float4 t4 = wr[i];
            w[4*i] = t4.x; w[4*i+1] = t4.y; w[4*i+2] = t4.z; w[4*i+3] = t4.w;
        }
    }
    float bv = bias[tid];

    for (int m0 = blockIdx.x * 32; m0 < M; m0 += gridDim.x * 32) {
        __syncthreads();
        for (int e = tid; e < 32 * 64; e += 192) {
            int ml = e >> 6, k = e & 63;
            int m = m0 + ml;
            Ts[ml][k] = (m < M) ? g_t[idx[m] * 64 + k] : 0.f;
        }
        __syncthreads();
        int mmax = min(32, M - m0);

        #pragma unroll
        for (int ml0 = 0; ml0 < 32; ml0 += 8) {
            float acc[8];
            #pragma unroll
            for (int u = 0; u < 8; ++u) acc[u] = bv;
            #pragma unroll
            for (int k4 = 0; k4 < 16; ++k4) {
                #pragma unroll
                for (int u = 0; u < 8; ++u) {
                    float4 t4 = *(const float4*)&Ts[ml0 + u][k4 * 4];
                    acc[u] += t4.x * w[4*k4];
                    acc[u] += t4.y * w[4*k4+1];
                    acc[u] += t4.z * w[4*k4+2];
                    acc[u] += t4.w * w[4*k4+3];
                }
            }
            #pragma unroll
            for (int u = 0; u < 8; ++u) {
                int ml = ml0 + u;
                if (ml < mmax) {
                    int m = m0 + ml;
                    if      (tid <  64) g_qs[m * 64 + tid]       = acc[u] * 0.125f;
                    else if (tid < 128) g_ks[m * 64 + tid - 64]  = acc[u];
                    else                g_vs[m * 64 + tid - 128] = acc[u];
                }
            }
        }
    }
}

// ---------------- attention partial (split-K flash) ----------------------------
// grid = (m-tiles stride, NSPLIT). Each block: 32 queries x one key chunk.
__global__ void __launch_bounds__(256) attn_part_kernel(int bi)
{
    int M = g_M3[bi];
    if ((int)blockIdx.x * 32 >= M) return;

    int chunk = (((M + 64 * NSPLIT - 1) / (64 * NSPLIT))) * 64;  // mult of 64
    int s  = blockIdx.y;
    int nb = s * chunk;
    int ne = min(nb + chunk, M);

    int tid = threadIdx.x;
    int r   = tid >> 3;
    int qq  = tid & 7;
    int cb  = qq * 8;

    __shared__ float Ksm[64][68];
    __shared__ float Vsm[64][68];
    __shared__ float Psm[32][65];

    for (int mb = blockIdx.x; mb * 32 < M; mb += gridDim.x) {
        int  m0    = mb * 32;
        int  m     = m0 + r;
        bool valid = (m < M);

        float qreg[64];
        {
            const float4* qp = (const float4*)(g_qs + (valid ? m : m0) * 64);
            #pragma unroll
            for (int i = 0; i < 16; ++i) {
                float4 v = qp[i];
                qreg[4*i] = v.x; qreg[4*i+1] = v.y; qreg[4*i+2] = v.z; qreg[4*i+3] = v.w;
            }
        }
        float y[8];
        #pragma unroll
        for (int j = 0; j < 8; ++j) y[j] = 0.f;
        float row_max = -1e30f, row_sum = 0.f;

        for (int n0 = nb; n0 < ne; n0 += 64) {
            __syncthreads();
            for (int e = tid; e < 64 * 16; e += 256) {
                int nl = e >> 4, k4 = e & 15;
                int n = n0 + nl;
                float4 kv = make_float4(0.f, 0.f, 0.f, 0.f);
                float4 vv = kv;
                if (n < ne) {
                    kv = *(const float4*)(g_ks + n * 64 + k4 * 4);
                    vv = *(const float4*)(g_vs + n * 64 + k4 * 4);
                }
                *(float4*)&Ksm[nl][k4 * 4] = kv;
                *(float4*)&Vsm[nl][k4 * 4] = vv;
            }
            __syncthreads();

            float sc[8];
            float tmax = -1e30f;
            #pragma unroll
            for (int kk = 0; kk < 8; ++kk) {
                int nl = 8 * kk + qq;
                float acc = 0.f;
                #pragma unroll
                for (int k4 = 0; k4 < 16; ++k4) {
                    float4 kvec = *(const float4*)&Ksm[nl][k4 * 4];
                    acc += qreg[4*k4]   * kvec.x;
                    acc += qreg[4*k4+1] * kvec.y;
                    acc += qreg[4*k4+2] * kvec.z;
                    acc += qreg[4*k4+3] * kvec.w;
                }
                if (n0 + nl >= ne) acc = -1e30f;
                sc[kk] = acc;
                tmax = fmaxf(tmax, acc);
            }
            #pragma unroll
            for (int o = 1; o < 8; o <<= 1)
                tmax = fmaxf(tmax, __shfl_xor_sync(0xffffffffu, tmax, o));

            float nmax = fmaxf(row_max, tmax);
            float corr = expf(row_max - nmax);
            float lsum = 0.f;
            #pragma unroll
            for (int kk = 0; kk < 8; ++kk) {
                float p = expf(sc[kk] - nmax);
                Psm[r][8 * kk + qq] = p;
                lsum += p;
            }
            #pragma unroll
            for (int o = 1; o < 8; o <<= 1)
                lsum += __shfl_xor_sync(0xffffffffu, lsum, o);
            row_sum = row_sum * corr + lsum;
            row_max = nmax;
            #pragma unroll
            for (int j = 0; j < 8; ++j) y[j] *= corr;
            __syncwarp();

            for (int nl = 0; nl < 64; ++nl) {
                float p = Psm[r][nl];
                float4 v0 = *(const float4*)&Vsm[nl][cb];
                float4 v1 = *(const float4*)&Vsm[nl][cb + 4];
                y[0] += p * v0.x; y[1] += p * v0.y;
                y[2] += p * v0.z; y[3] += p * v0.w;
                y[4] += p * v1.x; y[5] += p * v1.y;
                y[6] += p * v1.z; y[7] += p * v1.w;
            }
        }

        // write unnormalized partial + (m, l)
        float* pp = g_part + (((size_t)mb * NSPLIT + s) * 32 + r) * 68;
        *(float4*)(pp + cb)     = make_float4(y[0], y[1], y[2], y[3]);
        *(float4*)(pp + cb + 4) = make_float4(y[4], y[5], y[6], y[7]);
        if (qq == 0) { pp[64] = row_max; pp[65] = row_sum; }
        __syncthreads();    // smem safe before next mb iteration
    }
}

// ---------------- combine partials + proj + residual + dual scatter ------------
__global__ void __launch_bounds__(256) attn_combine_kernel(
    const float* __restrict__ Wp,  // [64][64]
    const float* __restrict__ bp,  // [64]
    int bi)
{
    int M = g_M3[bi];
    if ((int)blockIdx.x * 32 >= M) return;
    const int* __restrict__ idx = g_idx3 + bi * NTOK;

    int tid = threadIdx.x;
    int r   = tid >> 3;
    int qq  = tid & 7;
    int cb  = qq * 8;

    __shared__ float Ysm[32][68];

    // proj weights hoisted (thread: out channel oc, row group rb)
    int oc = tid & 63;
    int rb = tid >> 6;
    float wrow[64];
    {
        const float4* wr = (const float4*)(Wp + oc * 64);
        #pragma unroll
        for (int i = 0; i < 16; ++i) {
            float4 v = wr[i];
            wrow[4*i] = v.x; wrow[4*i+1] = v.y; wrow[4*i+2] = v.z; wrow[4*i+3] = v.w;
        }
    }
    float bv = bp[oc];

    for (int mb = blockIdx.x; mb * 32 < M; mb += gridDim.x) {
        int m0 = mb * 32;
        const float* pb = g_part + ((size_t)mb * NSPLIT) * 32 * 68 + r * 68;

        float gm = -1e30f;
        #pragma unroll
        for (int s = 0; s < NSPLIT; ++s)
            gm = fmaxf(gm, pb[s * 32 * 68 + 64]);

        float l = 0.f;
        float y[8];
        #pragma unroll
        for (int j = 0; j < 8; ++j) y[j] = 0.f;
        #pragma unroll
        for (int s = 0; s < NSPLIT; ++s) {
            const float* ps = pb + s * 32 * 68;
            float w = expf(ps[64] - gm);
            l += w * ps[65];
            float4 a = *(const float4*)(ps + cb);
            float4 b2 = *(const float4*)(ps + cb + 4);
            y[0] += w * a.x;  y[1] += w * a.y;
            y[2] += w * a.z;  y[3] += w * a.w;
            y[4] += w * b2.x; y[5] += w * b2.y;
            y[6] += w * b2.z; y[7] += w * b2.w;
        }
        float inv = 1.0f / l;
        *(float4*)&Ysm[r][cb]     = make_float4(y[0]*inv, y[1]*inv, y[2]*inv, y[3]*inv);
        *(float4*)&Ysm[r][cb + 4] = make_float4(y[4]*inv, y[5]*inv, y[6]*inv, y[7]*inv);
        __syncthreads();

        int mmax = min(32, M - m0);
        for (int rr = rb; rr < mmax; rr += 8) {
            int  rr2 = rr + 4;
            bool h2  = rr2 < mmax;
            int  rrs = h2 ? rr2 : rr;
            float a0 = bv, a1 = bv;
            #pragma unroll
            for (int k4 = 0; k4 < 16; ++k4) {
                float4 y0 = *(const float4*)&Ysm[rr ][k4 * 4];
                float4 y1 = *(const float4*)&Ysm[rrs][k4 * 4];
                a0 += y0.x * wrow[4*k4];   a1 += y1.x * wrow[4*k4];
                a0 += y0.y * wrow[4*k4+1]; a1 += y1.y * wrow[4*k4+1];
                a0 += y0.z * wrow[4*k4+2]; a1 += y1.z * wrow[4*k4+2];
                a0 += y0.w * wrow[4*k4+3]; a1 += y1.w * wrow[4*k4+3];
            }
            a0 += Ysm[rr ][oc];
            a1 += Ysm[rrs][oc];
            int tok0 = idx[m0 + rr];
            g_t [tok0 * 64 + oc]   = a0;
            g_hT[oc * NTOK + tok0] = a0;
            if (h2) {
                int tok1 = idx[m0 + rr2];
                g_t [tok1 * 64 + oc]   = a1;
                g_hT[oc * NTOK + tok1] = a1;
            }
        }
        __syncthreads();   // Ysm reuse guard
    }
}

// ---------------- trilinear x4 upsample: hT[c][32^3] -> out[c][128^3] ----------
__global__ void __launch_bounds__(256) upsample_kernel(float* __restrict__ out)
{
    const float S = 31.0f / 127.0f;
    int zo  = blockIdx.x;
    int c   = blockIdx.y;
    int tid = threadIdx.x;

    float pz = (float)zo * S;
    int z0 = (int)pz;
    int z1 = min(z0 + 1, 31);
    float wz = pz - (float)z0;

    __shared__ float F[1024];
    __shared__ float R[128][33];

    const float* p0 = g_hT + c * NTOK + z0 * 1024;
    const float* p1 = g_hT + c * NTOK + z1 * 1024;
    #pragma unroll
    for (int j = 0; j < 4; ++j) {
        int i = tid + 256 * j;
        float a = p0[i];
        F[i] = a + wz * (p1[i] - a);
    }
    __syncthreads();

    int w = tid >> 5, lane = tid & 31;

    #pragma unroll
    for (int j = 0; j < 16; ++j) {
        int yo = j * 8 + w;
        float py = (float)yo * S;
        int y0 = (int)py;
        int y1 = min(y0 + 1, 31);
        float wy = py - (float)y0;
        float a = F[y0 * 32 + lane];
        float b = F[y1 * 32 + lane];
        R[yo][lane] = a + wy * (b - a);
    }
    __syncthreads();

    int   x0[4], x1[4];
    float wx[4];
    #pragma unroll
    for (int j = 0; j < 4; ++j) {
        int xo = lane * 4 + j;
        float px = (float)xo * S;
        x0[j] = (int)px;
        x1[j] = min(x0[j] + 1, 31);
        wx[j] = px - (float)x0[j];
    }

    size_t obase = ((size_t)(c * 128 + zo)) * 16384;
    #pragma unroll
    for (int it = 0; it < 16; ++it) {
        int yo = it * 8 + w;
        const float* Rr = &R[yo][0];
        float4 o;
        #pragma unroll
        for (int j = 0; j < 4; ++j) {
            float r0 = Rr[x0[j]];
            (&o.x)[j] = r0 + wx[j] * (Rr[x1[j]] - r0);
        }
        *(float4*)(out + obase + (size_t)yo * 128 + lane * 4) = o;
    }
}

// ---------------- launch --------------------------------------------------------
extern "C" void kernel_launch(void* const* d_in, const int* in_sizes, int n_in,
                              void* d_out, int out_size)
{
    const float* x       = (const float*)d_in[0];
    const float* w_patch = (const float*)d_in[1];
    const float* b_patch = (const float*)d_in[2];
    const float* pos     = (const float*)d_in[3];

    const float* qkv_w[3]  = { (const float*)d_in[4],  (const float*)d_in[8],  (const float*)d_in[12] };
    const float* qkv_b[3]  = { (const float*)d_in[5],  (const float*)d_in[9],  (const float*)d_in[13] };
    const float* proj_w[3] = { (const float*)d_in[6],  (const float*)d_in[10], (const float*)d_in[14] };
    const float* proj_b[3] = { (const float*)d_in[7],  (const float*)d_in[11], (const float*)d_in[15] };

    conv_pos_kernel<<<NTOK / 32, 256>>>(x, w_patch, b_patch, pos);
    build_idx3_kernel<<<3, 1024>>>();

    for (int i = 0; i < 3; ++i) {
        qkv_kernel<<<64, 192>>>(qkv_w[i], qkv_b[i], i);
        attn_part_kernel<<<dim3(128, NSPLIT), 256>>>(i);
        attn_combine_kernel<<<128, 256>>>(proj_w[i], proj_b[i], i);
    }

    upsample_kernel<<<dim3(128, 64), 256>>>((float*)d_out);
}

// round 4
// speedup vs baseline: 1.2525x; 1.0003x over previous
#include <cuda_runtime.h>
#include <math.h>

#define NTOK 32768
#define CFEAT 64
#define NSPLIT 8

// ---------------- scratch (static device memory; no allocation) ----------------
__device__ float g_t  [NTOK * CFEAT];   // tokens [n][c]
__device__ float g_hT [NTOK * CFEAT];   // channel-major [c][n]
__device__ float g_qs [NTOK * CFEAT];
__device__ float g_ks [NTOK * CFEAT];
__device__ float g_vs [NTOK * CFEAT];
__device__ int   g_idx3[3 * NTOK];
__device__ int   g_M3[3];
// split-K partials: [m_tile up to 1024][split 8][row 32][68: 64 y, m, l]
__device__ float g_part[(NTOK / 32) * NSPLIT * 32 * 68];

// ---------------- fused patch conv + pos embed, dual-layout write --------------
__global__ void __launch_bounds__(256) conv_pos_kernel(
    const float* __restrict__ x,
    const float* __restrict__ W,    // [64][64]
    const float* __restrict__ b,
    const float* __restrict__ pos)  // [64][32768]
{
    __shared__ float P[32][68];
    __shared__ float O[64][33];
    int n0  = blockIdx.x * 32;
    int tid = threadIdx.x;

    #pragma unroll
    for (int j = 0; j < 8; ++j) {
        int e   = tid + 256 * j;
        int tok = e >> 6, k = e & 63;
        int n = n0 + tok;
        int z = n >> 10, y = (n >> 5) & 31, xx = n & 31;
        int dz = k >> 4, dy = (k >> 2) & 3, dx = k & 3;
        P[tok][k] = x[(4*z + dz) * 16384 + (4*y + dy) * 128 + (4*xx + dx)];
    }
    __syncthreads();

    int c = tid >> 2, sub = tid & 3;
    float w[64];
    {
        const float4* wp = (const float4*)(W + c * 64);
        #pragma unroll
        for (int i = 0; i < 16; ++i) {
            float4 t4 = wp[i];
            w[4*i] = t4.x; w[4*i+1] = t4.y; w[4*i+2] = t4.z; w[4*i+3] = t4.w;
        }
    }
    float bv = b[c];
    float acc[8];
    #pragma unroll
    for (int u = 0; u < 8; ++u) acc[u] = bv;

    #pragma unroll
    for (int k4 = 0; k4 < 16; ++k4) {
        #pragma unroll
        for (int u = 0; u < 8; ++u) {
            float4 p = *(const float4*)&P[u * 4 + sub][k4 * 4];
            acc[u] += p.x * w[4*k4];
            acc[u] += p.y * w[4*k4+1];
            acc[u] += p.z * w[4*k4+2];
            acc[u] += p.w * w[4*k4+3];
        }
    }
    #pragma unroll
    for (int u = 0; u < 8; ++u) O[c][u * 4 + sub] = acc[u];
    __syncthreads();

    #pragma unroll
    for (int j = 0; j < 8; ++j) {
        int e  = tid + 256 * j;
        int cc = e >> 5, nl = e & 31;
        float v = O[cc][nl] + pos[cc * NTOK + n0 + nl];
        O[cc][nl] = v;
        g_hT[cc * NTOK + n0 + nl] = v;
    }
    __syncthreads();

    #pragma unroll
    for (int j = 0; j < 8; ++j) {
        int e  = tid + 256 * j;
        int nl = e >> 6, cc = e & 63;
        g_t[(n0 + nl) * 64 + cc] = O[cc][nl];
    }
}

// ---------------- dilation index build: 3 blocks, one per dilation -------------
__global__ void build_idx3_kernel()
{
    __shared__ int cnt[1024];
    int bi  = blockIdx.x;
    int dil = (bi == 0) ? 2 : (bi == 1) ? 4 : 6;
    int*  out = g_idx3 + bi * NTOK;
    int t = threadIdx.x;
    int base = t * 32;
    float fd = (float)dil;

    unsigned flags = 0; int c = 0;
    for (int j = 0; j < 32; ++j) {
        int n = base + j;
        int z = (n >> 10) - 16, y = ((n >> 5) & 31) - 16, x = (n & 31) - 16;
        int ss = z*z + y*y + x*x;
        float d = sqrtf((float)ss);
        bool ok = (fmodf(d, fd) == 0.0f) || (ss == 0);
        if (ok) { flags |= (1u << j); c++; }
    }
    cnt[t] = c;
    __syncthreads();
    for (int off = 1; off < 1024; off <<= 1) {
        int v = (t >= off) ? cnt[t - off] : 0;
        __syncthreads();
        cnt[t] += v;
        __syncthreads();
    }
    int pos = cnt[t] - c;
    for (int j = 0; j < 32; ++j)
        if (flags & (1u << j)) out[pos++] = base + j;
    if (t == 1023) g_M3[bi] = cnt[1023];
}

// ---------------- QKV for selected tokens (scale 1/8 folded into Q) ------------
__global__ void __launch_bounds__(192) qkv_kernel(
    const float* __restrict__ W,    // [192][64]
    const float* __restrict__ bias, // [192]
    int bi)
{
    int M = g_M3[bi];
    if ((int)blockIdx.x * 32 >= M) return;
    const int* __restrict__ idx = g_idx3 + bi * NTOK;

    int tid = threadIdx.x;
    __shared__ float Ts[32][68];

    float w[64];
    {
        const float4* wr = (const float4*)(W + tid * 64);
        #pragma unroll
        for (int i = 0; i < 16; ++i) {
            float4 t4 = wr[i];
            w[4*i] = t4.x; w[4*i+1] = t4.y; w[4*i+2] = t4.z; w[4*i+3] = t4.w;
        }
    }
    float bv = bias[tid];

    for (int m0 = blockIdx.x * 32; m0 < M; m0 += gridDim.x * 32) {
        __syncthreads();
        for (int e = tid; e < 32 * 64; e += 192) {
            int ml = e >> 6, k = e & 63;
            int m = m0 + ml;
            Ts[ml][k] = (m < M) ? g_t[idx[m] * 64 + k] : 0.f;
        }
        __syncthreads();
        int mmax = min(32, M - m0);

        #pragma unroll
        for (int ml0 = 0; ml0 < 32; ml0 += 8) {
            float acc[8];
            #pragma unroll
            for (int u = 0; u < 8; ++u) acc[u] = bv;
            #pragma unroll
            for (int k4 = 0; k4 < 16; ++k4) {
                #pragma unroll
                for (int u = 0; u < 8; ++u) {
                    float4 t4 = *(const float4*)&Ts[ml0 + u][k4 * 4];
                    acc[u] += t4.x * w[4*k4];
                    acc[u] += t4.y * w[4*k4+1];
                    acc[u] += t4.z * w[4*k4+2];
                    acc[u] += t4.w * w[4*k4+3];
                }
            }
            #pragma unroll
            for (int u = 0; u < 8; ++u) {
                int ml = ml0 + u;
                if (ml < mmax) {
                    int m = m0 + ml;
                    if      (tid <  64) g_qs[m * 64 + tid]       = acc[u] * 0.125f;
                    else if (tid < 128) g_ks[m * 64 + tid - 64]  = acc[u];
                    else                g_vs[m * 64 + tid - 128] = acc[u];
                }
            }
        }
    }
}

// ---------------- attention partial (split-K flash) ----------------------------
// grid = (m-tiles stride, NSPLIT). Each block: 32 queries x one key chunk.
__global__ void __launch_bounds__(256) attn_part_kernel(int bi)
{
    int M = g_M3[bi];
    if ((int)blockIdx.x * 32 >= M) return;

    int chunk = (((M + 64 * NSPLIT - 1) / (64 * NSPLIT))) * 64;  // mult of 64
    int s  = blockIdx.y;
    int nb = s * chunk;
    int ne = min(nb + chunk, M);

    int tid = threadIdx.x;
    int r   = tid >> 3;
    int qq  = tid & 7;
    int cb  = qq * 8;

    __shared__ float Ksm[64][68];
    __shared__ float Vsm[64][68];
    __shared__ float Psm[32][65];

    for (int mb = blockIdx.x; mb * 32 < M; mb += gridDim.x) {
        int  m0    = mb * 32;
        int  m     = m0 + r;
        bool valid = (m < M);

        float qreg[64];
        {
            const float4* qp = (const float4*)(g_qs + (valid ? m : m0) * 64);
            #pragma unroll
            for (int i = 0; i < 16; ++i) {
                float4 v = qp[i];
                qreg[4*i] = v.x; qreg[4*i+1] = v.y; qreg[4*i+2] = v.z; qreg[4*i+3] = v.w;
            }
        }
        float y[8];
        #pragma unroll
        for (int j = 0; j < 8; ++j) y[j] = 0.f;
        float row_max = -1e30f, row_sum = 0.f;

        for (int n0 = nb; n0 < ne; n0 += 64) {
            __syncthreads();
            for (int e = tid; e < 64 * 16; e += 256) {
                int nl = e >> 4, k4 = e & 15;
                int n = n0 + nl;
                float4 kv = make_float4(0.f, 0.f, 0.f, 0.f);
                float4 vv = kv;
                if (n < ne) {
                    kv = *(const float4*)(g_ks + n * 64 + k4 * 4);
                    vv = *(const float4*)(g_vs + n * 64 + k4 * 4);
                }
                *(float4*)&Ksm[nl][k4 * 4] = kv;
                *(float4*)&Vsm[nl][k4 * 4] = vv;
            }
            __syncthreads();

            float sc[8];
            float tmax = -1e30f;
            #pragma unroll
            for (int kk = 0; kk < 8; ++kk) {
                int nl = 8 * kk + qq;
                float acc = 0.f;
                #pragma unroll
                for (int k4 = 0; k4 < 16; ++k4) {
                    float4 kvec = *(const float4*)&Ksm[nl][k4 * 4];
                    acc += qreg[4*k4]   * kvec.x;
                    acc += qreg[4*k4+1] * kvec.y;
                    acc += qreg[4*k4+2] * kvec.z;
                    acc += qreg[4*k4+3] * kvec.w;
                }
                if (n0 + nl >= ne) acc = -1e30f;
                sc[kk] = acc;
                tmax = fmaxf(tmax, acc);
            }
            #pragma unroll
            for (int o = 1; o < 8; o <<= 1)
                tmax = fmaxf(tmax, __shfl_xor_sync(0xffffffffu, tmax, o));

            float nmax = fmaxf(row_max, tmax);
            float corr = expf(row_max - nmax);
            float lsum = 0.f;
            #pragma unroll
            for (int kk = 0; kk < 8; ++kk) {
                float p = expf(sc[kk] - nmax);
                Psm[r][8 * kk + qq] = p;
                lsum += p;
            }
            #pragma unroll
            for (int o = 1; o < 8; o <<= 1)
                lsum += __shfl_xor_sync(0xffffffffu, lsum, o);
            row_sum = row_sum * corr + lsum;
            row_max = nmax;
            #pragma unroll
            for (int j = 0; j < 8; ++j) y[j] *= corr;
            __syncwarp();

            for (int nl = 0; nl < 64; ++nl) {
                float p = Psm[r][nl];
                float4 v0 = *(const float4*)&Vsm[nl][cb];
                float4 v1 = *(const float4*)&Vsm[nl][cb + 4];
                y[0] += p * v0.x; y[1] += p * v0.y;
                y[2] += p * v0.z; y[3] += p * v0.w;
                y[4] += p * v1.x; y[5] += p * v1.y;
                y[6] += p * v1.z; y[7] += p * v1.w;
            }
        }

        // write unnormalized partial + (m, l)
        float* pp = g_part + (((size_t)mb * NSPLIT + s) * 32 + r) * 68;
        *(float4*)(pp + cb)     = make_float4(y[0], y[1], y[2], y[3]);
        *(float4*)(pp + cb + 4) = make_float4(y[4], y[5], y[6], y[7]);
        if (qq == 0) { pp[64] = row_max; pp[65] = row_sum; }
        __syncthreads();    // smem safe before next mb iteration
    }
}

// ---------------- combine partials + proj + residual + dual scatter ------------
__global__ void __launch_bounds__(256) attn_combine_kernel(
    const float* __restrict__ Wp,  // [64][64]
    const float* __restrict__ bp,  // [64]
    int bi)
{
    int M = g_M3[bi];
    if ((int)blockIdx.x * 32 >= M) return;
    const int* __restrict__ idx = g_idx3 + bi * NTOK;

    int tid = threadIdx.x;
    int r   = tid >> 3;
    int qq  = tid & 7;
    int cb  = qq * 8;

    __shared__ float Ysm[32][68];

    // proj weights hoisted (thread: out channel oc, row group rb)
    int oc = tid & 63;
    int rb = tid >> 6;
    float wrow[64];
    {
        const float4* wr = (const float4*)(Wp + oc * 64);
        #pragma unroll
        for (int i = 0; i < 16; ++i) {
            float4 v = wr[i];
            wrow[4*i] = v.x; wrow[4*i+1] = v.y; wrow[4*i+2] = v.z; wrow[4*i+3] = v.w;
        }
    }
    float bv = bp[oc];

    for (int mb = blockIdx.x; mb * 32 < M; mb += gridDim.x) {
        int m0 = mb * 32;
        const float* pb = g_part + ((size_t)mb * NSPLIT) * 32 * 68 + r * 68;

        float gm = -1e30f;
        #pragma unroll
        for (int s = 0; s < NSPLIT; ++s)
            gm = fmaxf(gm, pb[s * 32 * 68 + 64]);

        float l = 0.f;
        float y[8];
        #pragma unroll
        for (int j = 0; j < 8; ++j) y[j] = 0.f;
        #pragma unroll
        for (int s = 0; s < NSPLIT; ++s) {
            const float* ps = pb + s * 32 * 68;
            float w = expf(ps[64] - gm);
            l += w * ps[65];
            float4 a = *(const float4*)(ps + cb);
            float4 b2 = *(const float4*)(ps + cb + 4);
            y[0] += w * a.x;  y[1] += w * a.y;
            y[2] += w * a.z;  y[3] += w * a.w;
            y[4] += w * b2.x; y[5] += w * b2.y;
            y[6] += w * b2.z; y[7] += w * b2.w;
        }
        float inv = 1.0f / l;
        *(float4*)&Ysm[r][cb]     = make_float4(y[0]*inv, y[1]*inv, y[2]*inv, y[3]*inv);
        *(float4*)&Ysm[r][cb + 4] = make_float4(y[4]*inv, y[5]*inv, y[6]*inv, y[7]*inv);
        __syncthreads();

        int mmax = min(32, M - m0);
        for (int rr = rb; rr < mmax; rr += 8) {
            int  rr2 = rr + 4;
            bool h2  = rr2 < mmax;
            int  rrs = h2 ? rr2 : rr;
            float a0 = bv, a1 = bv;
            #pragma unroll
            for (int k4 = 0; k4 < 16; ++k4) {
                float4 y0 = *(const float4*)&Ysm[rr ][k4 * 4];
                float4 y1 = *(const float4*)&Ysm[rrs][k4 * 4];
                a0 += y0.x * wrow[4*k4];   a1 += y1.x * wrow[4*k4];
                a0 += y0.y * wrow[4*k4+1]; a1 += y1.y * wrow[4*k4+1];
                a0 += y0.z * wrow[4*k4+2]; a1 += y1.z * wrow[4*k4+2];
                a0 += y0.w * wrow[4*k4+3]; a1 += y1.w * wrow[4*k4+3];
            }
            a0 += Ysm[rr ][oc];
            a1 += Ysm[rrs][oc];
            int tok0 = idx[m0 + rr];
            g_t [tok0 * 64 + oc]   = a0;
            g_hT[oc * NTOK + tok0] = a0;
            if (h2) {
                int tok1 = idx[m0 + rr2];
                g_t [tok1 * 64 + oc]   = a1;
                g_hT[oc * NTOK + tok1] = a1;
            }
        }
        __syncthreads();   // Ysm reuse guard
    }
}

// ---------------- trilinear x4 upsample: hT[c][32^3] -> out[c][128^3] ----------
__global__ void __launch_bounds__(256) upsample_kernel(float* __restrict__ out)
{
    const float S = 31.0f / 127.0f;
    int zo  = blockIdx.x;
    int c   = blockIdx.y;
    int tid = threadIdx.x;

    float pz = (float)zo * S;
    int z0 = (int)pz;
    int z1 = min(z0 + 1, 31);
    float wz = pz - (float)z0;

    __shared__ float F[1024];
    __shared__ float R[128][33];

    const float* p0 = g_hT + c * NTOK + z0 * 1024;
    const float* p1 = g_hT + c * NTOK + z1 * 1024;
    #pragma unroll
    for (int j = 0; j < 4; ++j) {
        int i = tid + 256 * j;
        float a = p0[i];
        F[i] = a + wz * (p1[i] - a);
    }
    __syncthreads();

    int w = tid >> 5, lane = tid & 31;

    #pragma unroll
    for (int j = 0; j < 16; ++j) {
        int yo = j * 8 + w;
        float py = (float)yo * S;
        int y0 = (int)py;
        int y1 = min(y0 + 1, 31);
        float wy = py - (float)y0;
        float a = F[y0 * 32 + lane];
        float b = F[y1 * 32 + lane];
        R[yo][lane] = a + wy * (b - a);
    }
    __syncthreads();

    int   x0[4], x1[4];
    float wx[4];
    #pragma unroll
    for (int j = 0; j < 4; ++j) {
        int xo = lane * 4 + j;
        float px = (float)xo * S;
        x0[j] = (int)px;
        x1[j] = min(x0[j] + 1, 31);
        wx[j] = px - (float)x0[j];
    }

    size_t obase = ((size_t)(c * 128 + zo)) * 16384;
    #pragma unroll
    for (int it = 0; it < 16; ++it) {
        int yo = it * 8 + w;
        const float* Rr = &R[yo][0];
        float4 o;
        #pragma unroll
        for (int j = 0; j < 4; ++j) {
            float r0 = Rr[x0[j]];
            (&o.x)[j] = r0 + wx[j] * (Rr[x1[j]] - r0);
        }
        *(float4*)(out + obase + (size_t)yo * 128 + lane * 4) = o;
    }
}

// ---------------- launch --------------------------------------------------------
extern "C" void kernel_launch(void* const* d_in, const int* in_sizes, int n_in,
                              void* d_out, int out_size)
{
    const float* x       = (const float*)d_in[0];
    const float* w_patch = (const float*)d_in[1];
    const float* b_patch = (const float*)d_in[2];
    const float* pos     = (const float*)d_in[3];

    const float* qkv_w[3]  = { (const float*)d_in[4],  (const float*)d_in[8],  (const float*)d_in[12] };
    const float* qkv_b[3]  = { (const float*)d_in[5],  (const float*)d_in[9],  (const float*)d_in[13] };
    const float* proj_w[3] = { (const float*)d_in[6],  (const float*)d_in[10], (const float*)d_in[14] };
    const float* proj_b[3] = { (const float*)d_in[7],  (const float*)d_in[11], (const float*)d_in[15] };

    conv_pos_kernel<<<NTOK / 32, 256>>>(x, w_patch, b_patch, pos);
    build_idx3_kernel<<<3, 1024>>>();

    for (int i = 0; i < 3; ++i) {
        qkv_kernel<<<64, 192>>>(qkv_w[i], qkv_b[i], i);
        attn_part_kernel<<<dim3(128, NSPLIT), 256>>>(i);
        attn_combine_kernel<<<128, 256>>>(proj_w[i], proj_b[i], i);
    }

    upsample_kernel<<<dim3(128, 64), 256>>>((float*)d_out);
}